// round 6
// baseline (speedup 1.0000x reference)
#include <cuda_runtime.h>

// NeuralVoxelField: trilinear interp of 2M random points into a 128^3 x16 fp32 grid.
//
// R5: counting-sort points into 4x4x4-voxel cells (32^3 = 32768 cells) so the
// interp pass has spatial locality: a warp's 8 points share a ~5^3 voxel
// neighborhood (~8KB) -> corner gathers hit L1 instead of DRAM.
// Pipeline (one stream, implicit ordering, graph-capturable):
//   zero -> histogram -> scan(1 block) -> scatter -> interp
// Scratch lives in __device__ globals (no allocation).

constexpr int Dg = 128, Hg = 128, Wg = 128;
constexpr float INV_VOXEL = 20.0f;   // 1/0.05
constexpr int CSHIFT = 2;            // 4 voxels per cell axis
constexpr int NCAX   = 32;           // 128 >> CSHIFT
constexpr int NCELLS = NCAX * NCAX * NCAX;  // 32768
constexpr int MAXN   = 2000000;

__device__ int    d_count[NCELLS];
__device__ int    d_cursor[NCELLS];
__device__ float4 d_sorted[MAXN];    // {gx, gy, gz, bitcast(origIdx)}

__device__ __forceinline__ int cell_of(float gx, float gy, float gz) {
    int vx = min(max(__float2int_rd(gx), 0), Dg - 1);
    int vy = min(max(__float2int_rd(gy), 0), Hg - 1);
    int vz = min(max(__float2int_rd(gz), 0), Wg - 1);
    return ((vx >> CSHIFT) * NCAX + (vy >> CSHIFT)) * NCAX + (vz >> CSHIFT);
}

__global__ void zero_kernel() {
    int i = blockIdx.x * blockDim.x + threadIdx.x;
    if (i < NCELLS) d_count[i] = 0;
}

__global__ void hist_kernel(const float* __restrict__ pts, int n) {
    int p = blockIdx.x * blockDim.x + threadIdx.x;
    if (p >= n) return;
    float gx = pts[p * 3 + 0] * INV_VOXEL;
    float gy = pts[p * 3 + 1] * INV_VOXEL;
    float gz = pts[p * 3 + 2] * INV_VOXEL;
    atomicAdd(&d_count[cell_of(gx, gy, gz)], 1);
}

// Single-block exclusive scan over 32768 counts (1024 threads x 32 cells each).
__global__ void scan_kernel() {
    __shared__ int s[1024];
    int tid = threadIdx.x;
    int base = tid * 32;
    int sum = 0;
    #pragma unroll
    for (int i = 0; i < 32; i++) sum += d_count[base + i];
    s[tid] = sum;
    __syncthreads();
    // Hillis-Steele inclusive scan over 1024 partials
    for (int off = 1; off < 1024; off <<= 1) {
        int v = 0;
        if (tid >= off) v = s[tid - off];
        __syncthreads();
        if (tid >= off) s[tid] += v;
        __syncthreads();
    }
    int run = (tid == 0) ? 0 : s[tid - 1];
    #pragma unroll
    for (int i = 0; i < 32; i++) {
        int c = d_count[base + i];
        d_cursor[base + i] = run;
        run += c;
    }
}

__global__ void scatter_kernel(const float* __restrict__ pts, int n) {
    int p = blockIdx.x * blockDim.x + threadIdx.x;
    if (p >= n) return;
    float gx = pts[p * 3 + 0] * INV_VOXEL;
    float gy = pts[p * 3 + 1] * INV_VOXEL;
    float gz = pts[p * 3 + 2] * INV_VOXEL;
    int cell = cell_of(gx, gy, gz);
    int pos = atomicAdd(&d_cursor[cell], 1);
    d_sorted[pos] = make_float4(gx, gy, gz, __int_as_float(p));
}

__device__ __forceinline__ float4 lerp4(float4 a, float4 b, float t) {
    float4 r;
    r.x = fmaf(b.x - a.x, t, a.x);
    r.y = fmaf(b.y - a.y, t, a.y);
    r.z = fmaf(b.z - a.z, t, a.z);
    r.w = fmaf(b.w - a.w, t, a.w);
    return r;
}

__global__ __launch_bounds__(256, 8)
void interp_kernel(const float4* __restrict__ values,  // grid as float4
                   float4* __restrict__ out,           // (N,16) as float4
                   int n)
{
    int t = blockIdx.x * blockDim.x + threadIdx.x;
    int p  = t >> 2;       // sorted point index
    int cg = t & 3;        // channel group
    if (p >= n) return;

    // 4 lanes of one point read the same 16B record -> L1 broadcast.
    float4 rec = d_sorted[p];
    float x = rec.x, y = rec.y, z = rec.z;
    int idx = __float_as_int(rec.w);

    int x0 = min(max(__float2int_rd(x), 0), Dg - 1);
    int y0 = min(max(__float2int_rd(y), 0), Hg - 1);
    int z0 = min(max(__float2int_rd(z), 0), Wg - 1);
    int x1 = min(x0 + 1, Dg - 1);
    int y1 = min(y0 + 1, Hg - 1);
    int z1 = min(z0 + 1, Wg - 1);

    float xd = x - (float)x0;
    float yd = y - (float)y0;
    float zd = z - (float)z0;

    int b00 = ((x0 * Hg + y0) * Wg) * 4 + cg;
    int b01 = ((x0 * Hg + y1) * Wg) * 4 + cg;
    int b10 = ((x1 * Hg + y0) * Wg) * 4 + cg;
    int b11 = ((x1 * Hg + y1) * Wg) * 4 + cg;
    int z0o = z0 * 4;
    int z1o = z1 * 4;

    float4 c000 = values[b00 + z0o];
    float4 c001 = values[b00 + z1o];
    float4 c010 = values[b01 + z0o];
    float4 c011 = values[b01 + z1o];
    float4 c100 = values[b10 + z0o];
    float4 c101 = values[b10 + z1o];
    float4 c110 = values[b11 + z0o];
    float4 c111 = values[b11 + z1o];

    float4 c00 = lerp4(c000, c100, xd);
    float4 c01 = lerp4(c001, c101, xd);
    float4 c10 = lerp4(c010, c110, xd);
    float4 c11 = lerp4(c011, c111, xd);

    float4 c0 = lerp4(c00, c10, yd);
    float4 c1 = lerp4(c01, c11, yd);

    // Original-order output slot; 64B contiguous per point, evict-first.
    __stcs(&out[idx * 4 + cg], lerp4(c0, c1, zd));
}

extern "C" void kernel_launch(void* const* d_in, const int* in_sizes, int n_in,
                              void* d_out, int out_size) {
    const float*  points = (const float*)d_in[0];    // (N,3) fp32
    const float4* values = (const float4*)d_in[1];   // (128,128,128,16) fp32
    float4* out = (float4*)d_out;

    int n = in_sizes[0] / 3;
    if (n > MAXN) n = MAXN;

    int T = 256;
    zero_kernel<<<(NCELLS + T - 1) / T, T>>>();
    hist_kernel<<<(n + T - 1) / T, T>>>(points, n);
    scan_kernel<<<1, 1024>>>();
    scatter_kernel<<<(n + T - 1) / T, T>>>(points, n);
    long long total = (long long)n * 4;
    interp_kernel<<<(int)((total + T - 1) / T), T>>>(values, out, n);
}

// round 7
// speedup vs baseline: 1.4778x; 1.4778x over previous
#include <cuda_runtime.h>

// NeuralVoxelField: trilinear interp of 2M random points into a 128^3 x16 fp32 grid.
//
// R6: multi-pass slab filtering. The grid is 134MB, L2 is 126MB -> a single
// pass thrashes (R4: 815MB DRAM). Split the x-axis into 2 slabs of 67MB each
// and run the interp kernel once per slab, processing only points whose base
// x-cell lies in that slab. Each pass's gather working set is L2-resident, so
// the 512MB/pass of gather traffic hits L2 (~87%) instead of DRAM.
// No point reordering, no scratch, no atomics.

constexpr int Dg = 128, Hg = 128, Wg = 128;
constexpr float INV_VOXEL = 20.0f;  // 1/0.05

__device__ __forceinline__ float4 lerp4(float4 a, float4 b, float t) {
    float4 r;
    r.x = fmaf(b.x - a.x, t, a.x);
    r.y = fmaf(b.y - a.y, t, a.y);
    r.z = fmaf(b.z - a.z, t, a.z);
    r.w = fmaf(b.w - a.w, t, a.w);
    return r;
}

__global__ __launch_bounds__(256, 8)
void trilerp_slab_kernel(const float* __restrict__ points,
                         const float4* __restrict__ values,  // grid as float4
                         float4* __restrict__ out,           // (N,16) as float4
                         int n, int x_lo, int x_hi)
{
    int t = blockIdx.x * blockDim.x + threadIdx.x;
    int p  = t >> 2;        // point index
    int cg = t & 3;         // channel group (4 floats)
    if (p >= n) return;

    // 4 lanes of a point read the same 12B -> L1 broadcast. Evict-first:
    // points are re-read once per pass but never reused within a pass.
    float x = __ldcs(&points[p * 3 + 0]) * INV_VOXEL;
    float y = __ldcs(&points[p * 3 + 1]) * INV_VOXEL;
    float z = __ldcs(&points[p * 3 + 2]) * INV_VOXEL;

    int x0 = min(max(__float2int_rd(x), 0), Dg - 1);
    if (x0 < x_lo || x0 >= x_hi) return;   // not this slab's point

    int y0 = min(max(__float2int_rd(y), 0), Hg - 1);
    int z0 = min(max(__float2int_rd(z), 0), Wg - 1);
    int x1 = min(x0 + 1, Dg - 1);
    int y1 = min(y0 + 1, Hg - 1);
    int z1 = min(z0 + 1, Wg - 1);

    float xd = x - (float)x0;
    float yd = y - (float)y0;
    float zd = z - (float)z0;

    // voxel -> float4 index: lin*4 + cg (16 floats = 4 float4 per voxel)
    int b00 = ((x0 * Hg + y0) * Wg) * 4 + cg;
    int b01 = ((x0 * Hg + y1) * Wg) * 4 + cg;
    int b10 = ((x1 * Hg + y0) * Wg) * 4 + cg;
    int b11 = ((x1 * Hg + y1) * Wg) * 4 + cg;
    int z0o = z0 * 4;
    int z1o = z1 * 4;

    // All 8 gathers issued up front (MLP=8); default caching (L2 reuse set).
    float4 c000 = values[b00 + z0o];
    float4 c001 = values[b00 + z1o];
    float4 c010 = values[b01 + z0o];
    float4 c011 = values[b01 + z1o];
    float4 c100 = values[b10 + z0o];
    float4 c101 = values[b10 + z1o];
    float4 c110 = values[b11 + z0o];
    float4 c111 = values[b11 + z1o];

    float4 c00 = lerp4(c000, c100, xd);
    float4 c01 = lerp4(c001, c101, xd);
    float4 c10 = lerp4(c010, c110, xd);
    float4 c11 = lerp4(c011, c111, xd);

    float4 c0 = lerp4(c00, c10, yd);
    float4 c1 = lerp4(c01, c11, yd);

    // Output written once, never re-read -> evict-first.
    __stcs(&out[p * 4 + cg], lerp4(c0, c1, zd));
}

extern "C" void kernel_launch(void* const* d_in, const int* in_sizes, int n_in,
                              void* d_out, int out_size) {
    const float*  points = (const float*)d_in[0];    // (N,3) fp32
    const float4* values = (const float4*)d_in[1];   // (128,128,128,16) fp32
    float4* out = (float4*)d_out;

    int n = in_sizes[0] / 3;
    long long total = (long long)n * 4;
    int T = 256;
    int blocks = (int)((total + T - 1) / T);

    // Two slabs: x-cell in [0,64) then [64,128). Sequential launches on one
    // stream; each pass's 67MB grid slab stays L2-resident.
    trilerp_slab_kernel<<<blocks, T>>>(points, values, out, n, 0, 64);
    trilerp_slab_kernel<<<blocks, T>>>(points, values, out, n, 64, 128);
}

// round 8
// speedup vs baseline: 1.8459x; 1.2490x over previous
#include <cuda_runtime.h>
#include <cuda_fp16.h>

// NeuralVoxelField: trilinear interp of 2M random points into a 128^3 x16 grid.
//
// R7: the fp32 grid (134MB) can't stay resident in L2 (126MB) -> convert it to
// fp16 (64MB) once per launch into __device__ scratch. The fp16 grid fits L2
// with room to spare, so a SINGLE full-lane interp pass has every corner
// gather hit L2. Gather traffic also halves (256B/point). All interpolation
// arithmetic stays fp32; only the stored corner values are fp16.

constexpr int Dg = 128, Hg = 128, Wg = 128, Cg = 16;
constexpr float INV_VOXEL = 20.0f;               // 1/0.05
constexpr int NVOX   = Dg * Hg * Wg;             // 2,097,152
constexpr int NHALF  = NVOX * Cg;                // 33,554,432 halves (64MB)
constexpr int NELEM4 = NHALF / 4;                // float4 count of the grid

__device__ __align__(16) __half d_grid_h[NHALF];

// ---- pass 1: fp32 grid -> fp16 scratch (streaming) ----
__global__ __launch_bounds__(256)
void convert_kernel(const float4* __restrict__ values) {
    int i = blockIdx.x * blockDim.x + threadIdx.x;
    if (i >= NELEM4) return;
    float4 v = __ldcs(&values[i]);               // evict-first: read once
    __half2 a = __float22half2_rn(make_float2(v.x, v.y));
    __half2 b = __float22half2_rn(make_float2(v.z, v.w));
    uint2 u;
    u.x = *reinterpret_cast<unsigned int*>(&a);
    u.y = *reinterpret_cast<unsigned int*>(&b);
    // default store: we WANT this resident in L2 for the interp pass
    *reinterpret_cast<uint2*>(&d_grid_h[(size_t)i * 4]) = u;
}

// ---- pass 2: interp ----
__device__ __forceinline__ float4 h4_to_f4(uint2 u) {
    __half2 h0 = *reinterpret_cast<__half2*>(&u.x);
    __half2 h1 = *reinterpret_cast<__half2*>(&u.y);
    float2 f0 = __half22float2(h0);
    float2 f1 = __half22float2(h1);
    return make_float4(f0.x, f0.y, f1.x, f1.y);
}

__device__ __forceinline__ float4 lerp4(float4 a, float4 b, float t) {
    float4 r;
    r.x = fmaf(b.x - a.x, t, a.x);
    r.y = fmaf(b.y - a.y, t, a.y);
    r.z = fmaf(b.z - a.z, t, a.z);
    r.w = fmaf(b.w - a.w, t, a.w);
    return r;
}

__global__ __launch_bounds__(256, 8)
void interp_kernel(const float* __restrict__ points,
                   float4* __restrict__ out,     // (N,16) fp32 as float4
                   int n)
{
    int t = blockIdx.x * blockDim.x + threadIdx.x;
    int p  = t >> 2;        // point index
    int cg = t & 3;         // channel group (4 channels)
    if (p >= n) return;

    // 4 lanes of one point read the same 12B -> L1 broadcast; evict-first.
    float x = __ldcs(&points[p * 3 + 0]) * INV_VOXEL;
    float y = __ldcs(&points[p * 3 + 1]) * INV_VOXEL;
    float z = __ldcs(&points[p * 3 + 2]) * INV_VOXEL;

    int x0 = min(max(__float2int_rd(x), 0), Dg - 1);
    int y0 = min(max(__float2int_rd(y), 0), Hg - 1);
    int z0 = min(max(__float2int_rd(z), 0), Wg - 1);
    int x1 = min(x0 + 1, Dg - 1);
    int y1 = min(y0 + 1, Hg - 1);
    int z1 = min(z0 + 1, Wg - 1);

    float xd = x - (float)x0;
    float yd = y - (float)y0;
    float zd = z - (float)z0;

    // half-element offsets: voxel lin * 16 channels + cg*4
    int b00 = ((x0 * Hg + y0) * Wg) * Cg + cg * 4;
    int b01 = ((x0 * Hg + y1) * Wg) * Cg + cg * 4;
    int b10 = ((x1 * Hg + y0) * Wg) * Cg + cg * 4;
    int b11 = ((x1 * Hg + y1) * Wg) * Cg + cg * 4;
    int z0o = z0 * Cg;
    int z1o = z1 * Cg;

    const __half* g = d_grid_h;
    // Issue all 8 gathers (8B each, 32B contiguous per point across 4 lanes).
    uint2 u000 = *reinterpret_cast<const uint2*>(g + b00 + z0o);
    uint2 u001 = *reinterpret_cast<const uint2*>(g + b00 + z1o);
    uint2 u010 = *reinterpret_cast<const uint2*>(g + b01 + z0o);
    uint2 u011 = *reinterpret_cast<const uint2*>(g + b01 + z1o);
    uint2 u100 = *reinterpret_cast<const uint2*>(g + b10 + z0o);
    uint2 u101 = *reinterpret_cast<const uint2*>(g + b10 + z1o);
    uint2 u110 = *reinterpret_cast<const uint2*>(g + b11 + z0o);
    uint2 u111 = *reinterpret_cast<const uint2*>(g + b11 + z1o);

    float4 c00 = lerp4(h4_to_f4(u000), h4_to_f4(u100), xd);
    float4 c01 = lerp4(h4_to_f4(u001), h4_to_f4(u101), xd);
    float4 c10 = lerp4(h4_to_f4(u010), h4_to_f4(u110), xd);
    float4 c11 = lerp4(h4_to_f4(u011), h4_to_f4(u111), xd);

    float4 c0 = lerp4(c00, c10, yd);
    float4 c1 = lerp4(c01, c11, yd);

    // Output written once, never re-read -> evict-first (protects grid in L2).
    __stcs(&out[p * 4 + cg], lerp4(c0, c1, zd));
}

extern "C" void kernel_launch(void* const* d_in, const int* in_sizes, int n_in,
                              void* d_out, int out_size) {
    const float*  points = (const float*)d_in[0];    // (N,3) fp32
    const float4* values = (const float4*)d_in[1];   // (128,128,128,16) fp32
    float4* out = (float4*)d_out;

    int n = in_sizes[0] / 3;
    int T = 256;

    convert_kernel<<<(NELEM4 + T - 1) / T, T>>>(values);

    long long total = (long long)n * 4;
    interp_kernel<<<(int)((total + T - 1) / T), T>>>(points, out, n);
}

// round 9
// speedup vs baseline: 2.0711x; 1.1220x over previous
#include <cuda_runtime.h>
#include <cuda_fp16.h>

// NeuralVoxelField: trilinear interp of 2M random points into a 128^3 x16 grid.
//
// R8: fp16 grid in __device__ scratch (fits L2) as before; interp restructured:
//   - voxels (z0,z0+1) are contiguous 64B in the fp16 grid -> load each (x,y)
//     corner's z-PAIR as one LDG.128 per lane (4 lanes x 16B = 64B).
//     4 wide loads per lane instead of 8 narrow ones; ~25% fewer L1 wavefronts.
//   - lane l owns z-level (l>>1) and channels (l&1)*8..+7: bilerp in x,y is
//     fully in-lane (fp32), then one 8-float shfl_xor(2) sums the two z-levels
//     (each lane pre-multiplies by its own z-weight).
//   - z-clamp at z0=127: load pair at zp=min(z0,126), weights (0,1).

constexpr int Dg = 128, Hg = 128, Wg = 128, Cg = 16;
constexpr float INV_VOXEL = 20.0f;               // 1/0.05
constexpr int NVOX   = Dg * Hg * Wg;
constexpr int NHALF  = NVOX * Cg;                // 64MB of halves
constexpr int NELEM4 = NHALF / 4;

__device__ __align__(16) __half d_grid_h[NHALF];

// ---- pass 1: fp32 grid -> fp16 scratch (streaming, DRAM-roofline) ----
__global__ __launch_bounds__(256)
void convert_kernel(const float4* __restrict__ values) {
    int i = blockIdx.x * blockDim.x + threadIdx.x;
    if (i >= NELEM4) return;
    float4 v = __ldcs(&values[i]);               // evict-first: read once
    __half2 a = __float22half2_rn(make_float2(v.x, v.y));
    __half2 b = __float22half2_rn(make_float2(v.z, v.w));
    uint2 u;
    u.x = *reinterpret_cast<unsigned int*>(&a);
    u.y = *reinterpret_cast<unsigned int*>(&b);
    *reinterpret_cast<uint2*>(&d_grid_h[(size_t)i * 4]) = u;  // want L2-resident
}

// expand 8 packed halves (uint4) -> 8 floats
__device__ __forceinline__ void h8_to_f8(const uint4& q, float* f) {
    float2 a = __half22float2(*reinterpret_cast<const __half2*>(&q.x));
    float2 b = __half22float2(*reinterpret_cast<const __half2*>(&q.y));
    float2 c = __half22float2(*reinterpret_cast<const __half2*>(&q.z));
    float2 d = __half22float2(*reinterpret_cast<const __half2*>(&q.w));
    f[0]=a.x; f[1]=a.y; f[2]=b.x; f[3]=b.y; f[4]=c.x; f[5]=c.y; f[6]=d.x; f[7]=d.y;
}

__global__ __launch_bounds__(256, 6)
void interp_kernel(const float* __restrict__ points,
                   float4* __restrict__ out,     // (N,16) fp32 as float4
                   int n)
{
    int t = blockIdx.x * blockDim.x + threadIdx.x;
    int p = t >> 2;        // point index
    int l = t & 3;         // lane-in-point: z-level = l>>1, channel half = l&1
    if (p >= n) return;

    // 4 lanes of one point read the same 12B -> L1 broadcast; evict-first.
    float x = __ldcs(&points[p * 3 + 0]) * INV_VOXEL;
    float y = __ldcs(&points[p * 3 + 1]) * INV_VOXEL;
    float z = __ldcs(&points[p * 3 + 2]) * INV_VOXEL;

    int x0 = min(max(__float2int_rd(x), 0), Dg - 1);
    int y0 = min(max(__float2int_rd(y), 0), Hg - 1);
    int z0 = min(max(__float2int_rd(z), 0), Wg - 1);
    int x1 = min(x0 + 1, Dg - 1);
    int y1 = min(y0 + 1, Hg - 1);
    int zp = min(z0, Wg - 2);          // aligned-ish pair base (z0 or 126)

    float xd = x - (float)x0;
    float yd = y - (float)y0;
    float zd = z - (float)z0;

    // z-pair weights: normally (1-zd, zd); clamped case z0==127 -> (0, 1)
    float w1 = (z0 == Wg - 1) ? 1.0f : zd;
    float w0 = 1.0f - w1;
    int   v  = l >> 1;                  // my z-level within the pair
    float wa = v ? w1 : w0;             // my own z-weight

    // half-element addresses: corner pair base + lane chunk (l*8 halves = 16B)
    int zb  = zp * Cg + l * 8;
    int a00 = ((x0 * Hg + y0) * Wg) * Cg + zb;
    int a01 = ((x0 * Hg + y1) * Wg) * Cg + zb;
    int a10 = ((x1 * Hg + y0) * Wg) * Cg + zb;
    int a11 = ((x1 * Hg + y1) * Wg) * Cg + zb;

    const __half* g = d_grid_h;
    // 4 wide gathers, issued up front (MLP=4 x 16B/lane, 64B/point/corner)
    uint4 q00 = *reinterpret_cast<const uint4*>(g + a00);
    uint4 q01 = *reinterpret_cast<const uint4*>(g + a01);
    uint4 q10 = *reinterpret_cast<const uint4*>(g + a10);
    uint4 q11 = *reinterpret_cast<const uint4*>(g + a11);

    float f00[8], f01[8], f10[8], f11[8];
    h8_to_f8(q00, f00);
    h8_to_f8(q01, f01);
    h8_to_f8(q10, f10);
    h8_to_f8(q11, f11);

    // in-lane x/y bilerp (fp32) + my z-weight
    float m[8];
    #pragma unroll
    for (int i = 0; i < 8; i++) {
        float t0 = fmaf(f01[i] - f00[i], yd, f00[i]);   // y-lerp @ x0
        float t1 = fmaf(f11[i] - f10[i], yd, f10[i]);   // y-lerp @ x1
        m[i] = fmaf(t1 - t0, xd, t0) * wa;              // x-lerp * z-weight
    }

    // sum the two z-levels: partner lane (l^2) holds the other level,
    // already multiplied by ITS weight.
    float c[8];
    #pragma unroll
    for (int i = 0; i < 8; i++)
        c[i] = m[i] + __shfl_xor_sync(0xffffffffu, m[i], 2);

    // lanes (0,2) both hold ch0-7, lanes (1,3) hold ch8-15; each stores 4:
    //   lane0 -> ch0-3 (slot0), lane2 -> ch4-7 (slot1),
    //   lane1 -> ch8-11 (slot2), lane3 -> ch12-15 (slot3)
    int slot = ((l & 1) << 1) | v;
    const float* s = c + v * 4;
    __stcs(&out[p * 4 + slot], make_float4(s[0], s[1], s[2], s[3]));
}

extern "C" void kernel_launch(void* const* d_in, const int* in_sizes, int n_in,
                              void* d_out, int out_size) {
    const float*  points = (const float*)d_in[0];    // (N,3) fp32
    const float4* values = (const float4*)d_in[1];   // (128,128,128,16) fp32
    float4* out = (float4*)d_out;

    int n = in_sizes[0] / 3;
    int T = 256;

    convert_kernel<<<(NELEM4 + T - 1) / T, T>>>(values);

    long long total = (long long)n * 4;
    interp_kernel<<<(int)((total + T - 1) / T), T>>>(points, out, n);
}

// round 11
// speedup vs baseline: 2.0787x; 1.0037x over previous
#include <cuda_runtime.h>
#include <cuda_fp16.h>

// NeuralVoxelField: trilinear interp of 2M random points into a 128^3 x16 grid.
//
// R10 = R9 with the evict-last gather fixed for sm_103a:
//  bare .L2::evict_last on ld requires 32B vectors, so use
//  createpolicy.fractional.L2::evict_last + ld.global.nc.L2::cache_hint.v4.u32
//  (policy created once per thread). Everything else as R9:
//  fp16 grid scratch (64MB, L2-resident), z-pair wide loads, half2 x/y lerp,
//  fp32 z-combine via lane-pair shfl, evict-first output stores.

constexpr int Dg = 128, Hg = 128, Wg = 128, Cg = 16;
constexpr float INV_VOXEL = 20.0f;               // 1/0.05
constexpr int NVOX   = Dg * Hg * Wg;
constexpr int NHALF  = NVOX * Cg;                // 64MB of halves
constexpr int NELEM4 = NHALF / 4;

__device__ __align__(16) __half d_grid_h[NHALF];

// ---- pass 1: fp32 grid -> fp16 scratch (streaming, DRAM-roofline) ----
__global__ __launch_bounds__(256)
void convert_kernel(const float4* __restrict__ values) {
    int i = blockIdx.x * blockDim.x + threadIdx.x;
    if (i >= NELEM4) return;
    float4 v = __ldcs(&values[i]);               // evict-first: read once
    __half2 a = __float22half2_rn(make_float2(v.x, v.y));
    __half2 b = __float22half2_rn(make_float2(v.z, v.w));
    uint2 u;
    u.x = *reinterpret_cast<unsigned int*>(&a);
    u.y = *reinterpret_cast<unsigned int*>(&b);
    *reinterpret_cast<uint2*>(&d_grid_h[(size_t)i * 4]) = u;  // want L2-resident
}

// one-time per-thread L2 evict-last policy
__device__ __forceinline__ unsigned long long mk_evict_last_policy() {
    unsigned long long pol;
    asm("createpolicy.fractional.L2::evict_last.b64 %0, 1.0;" : "=l"(pol));
    return pol;
}

// 16B gather with L2 evict-last cache hint (grid is the reuse set)
__device__ __forceinline__ uint4 ldg_el(const __half* p, unsigned long long pol) {
    uint4 q;
    asm volatile("ld.global.nc.L2::cache_hint.v4.u32 {%0,%1,%2,%3}, [%4], %5;"
                 : "=r"(q.x), "=r"(q.y), "=r"(q.z), "=r"(q.w)
                 : "l"(p), "l"(pol));
    return q;
}

// out[i] = a[i] + (b[i]-a[i])*w   (4x half2)
__device__ __forceinline__ void lerp_h2x4(const uint4& a, const uint4& b,
                                          __half2 w, __half2* o) {
    const __half2* ah = reinterpret_cast<const __half2*>(&a);
    const __half2* bh = reinterpret_cast<const __half2*>(&b);
    #pragma unroll
    for (int i = 0; i < 4; i++)
        o[i] = __hfma2(__hsub2(bh[i], ah[i]), w, ah[i]);
}

__global__ __launch_bounds__(256, 6)
void interp_kernel(const float* __restrict__ points,
                   float4* __restrict__ out,     // (N,16) fp32 as float4
                   int n)
{
    int t = blockIdx.x * blockDim.x + threadIdx.x;
    int p = t >> 2;        // point index
    int l = t & 3;         // lane-in-point: z-level = l>>1, channel half = l&1
    if (p >= n) return;

    // 4 lanes of one point read the same 12B -> L1 broadcast; evict-first.
    float x = __ldcs(&points[p * 3 + 0]) * INV_VOXEL;
    float y = __ldcs(&points[p * 3 + 1]) * INV_VOXEL;
    float z = __ldcs(&points[p * 3 + 2]) * INV_VOXEL;

    int x0 = min(max(__float2int_rd(x), 0), Dg - 1);
    int y0 = min(max(__float2int_rd(y), 0), Hg - 1);
    int z0 = min(max(__float2int_rd(z), 0), Wg - 1);
    int x1 = min(x0 + 1, Dg - 1);
    int y1 = min(y0 + 1, Hg - 1);
    int zp = min(z0, Wg - 2);          // z-pair base (z0 or 126)

    float xd = x - (float)x0;
    float yd = y - (float)y0;
    float zd = z - (float)z0;

    // z-pair weights: normally (1-zd, zd); clamped z0==127 -> (0, 1)
    float w1 = (z0 == Wg - 1) ? 1.0f : zd;
    int   v  = l >> 1;                  // my z-level within the pair
    float wa = v ? w1 : (1.0f - w1);    // my z-weight

    // half-element addresses: corner pair base + lane chunk (l*8 halves = 16B)
    int zb  = zp * Cg + l * 8;
    int a00 = ((x0 * Hg + y0) * Wg) * Cg + zb;
    int a01 = ((x0 * Hg + y1) * Wg) * Cg + zb;
    int a10 = ((x1 * Hg + y0) * Wg) * Cg + zb;
    int a11 = ((x1 * Hg + y1) * Wg) * Cg + zb;

    unsigned long long pol = mk_evict_last_policy();
    const __half* g = d_grid_h;
    // 4 wide gathers, MLP=4, evict-last in L2
    uint4 q00 = ldg_el(g + a00, pol);
    uint4 q01 = ldg_el(g + a01, pol);
    uint4 q10 = ldg_el(g + a10, pol);
    uint4 q11 = ldg_el(g + a11, pol);

    __half2 yd2 = __float2half2_rn(yd);
    __half2 xd2 = __float2half2_rn(xd);

    // y-lerp (half2): corners -> two x-levels
    __half2 t0[4], t1[4];
    lerp_h2x4(q00, q01, yd2, t0);      // @x0
    lerp_h2x4(q10, q11, yd2, t1);      // @x1

    // x-lerp (half2)
    __half2 r[4];
    #pragma unroll
    for (int i = 0; i < 4; i++)
        r[i] = __hfma2(__hsub2(t1[i], t0[i]), xd2, t0[i]);

    // convert to fp32, apply my z-weight
    float m[8];
    #pragma unroll
    for (int i = 0; i < 4; i++) {
        float2 f = __half22float2(r[i]);
        m[i * 2 + 0] = f.x * wa;
        m[i * 2 + 1] = f.y * wa;
    }

    // sum the two z-levels (partner lane l^2 holds the other, pre-weighted)
    float c[8];
    #pragma unroll
    for (int i = 0; i < 8; i++)
        c[i] = m[i] + __shfl_xor_sync(0xffffffffu, m[i], 2);

    // lanes (0,2) hold ch0-7, lanes (1,3) hold ch8-15; each stores 4 channels:
    //   lane0->slot0 (ch0-3), lane2->slot1 (ch4-7),
    //   lane1->slot2 (ch8-11), lane3->slot3 (ch12-15)
    int slot = ((l & 1) << 1) | v;
    const float* s = c + v * 4;
    __stcs(&out[p * 4 + slot], make_float4(s[0], s[1], s[2], s[3]));
}

extern "C" void kernel_launch(void* const* d_in, const int* in_sizes, int n_in,
                              void* d_out, int out_size) {
    const float*  points = (const float*)d_in[0];    // (N,3) fp32
    const float4* values = (const float4*)d_in[1];   // (128,128,128,16) fp32
    float4* out = (float4*)d_out;

    int n = in_sizes[0] / 3;
    int T = 256;

    convert_kernel<<<(NELEM4 + T - 1) / T, T>>>(values);

    long long total = (long long)n * 4;
    interp_kernel<<<(int)((total + T - 1) / T), T>>>(points, out, n);
}